// round 14
// baseline (speedup 1.0000x reference)
#include <cuda_runtime.h>
#include <cuda_fp16.h>
#include <cstdint>

#define FRONT 3072
#define EMBED 768
#define TOKENS 16384

// ---------------- device scratch (no dynamic alloc allowed) ----------------
__device__ __half g_W1h[EMBED * FRONT];                 // fp16 weights
__device__ __half g_W2h[EMBED * EMBED];
__device__ __half g_A[(size_t)TOKENS * FRONT];          // gathered embed, fp16
__device__ __half g_Y[(size_t)TOKENS * EMBED];          // GELU(h1), fp16

// ---------------- tiling ----------------
constexpr int BM = 128;
constexpr int BN = 128;
constexpr int BK = 32;              // fp16 K columns per stage (2 k16 steps)
constexpr int THREADS = 128;        // 4 warps, each 64x64
constexpr int STAGES = 3;

// 80-byte pitch = 5 x 16B units (odd) -> any 8 consecutive rows at a fixed 16B
// chunk column hit 8 distinct bank groups: ldmatrix conflict-free, NO swizzle.
constexpr int ROWB   = 80;
constexpr int SROWS  = BM + BN;             // 256 rows per stage (A then B)
constexpr int STAGE  = SROWS * ROWB;        // 20480 B
constexpr int SMEM_TOTAL = STAGES * STAGE;  // 61440 B -> 2 CTAs/SM
constexpr int OFF_A = 0;
constexpr int OFF_B = BM * ROWB;            // B rows start at row 128

// ---------------- PTX helpers (plain compute_103-legal) ----------------
__device__ __forceinline__ uint32_t smem_u32(const void* p) {
    uint32_t a;
    asm("{ .reg .u64 t; cvta.to.shared.u64 t, %1; cvt.u32.u64 %0, t; }" : "=r"(a) : "l"(p));
    return a;
}
__device__ __forceinline__ void cp16(uint32_t s, const void* g) {
    asm volatile("cp.async.cg.shared.global [%0], [%1], 16;" :: "r"(s), "l"(g));
}
__device__ __forceinline__ void cp_commit() {
    asm volatile("cp.async.commit_group;");
}
__device__ __forceinline__ void ldm4(uint32_t r[4], uint32_t a) {
    asm volatile("ldmatrix.sync.aligned.m8n8.x4.shared.b16 {%0,%1,%2,%3}, [%4];"
                 : "=r"(r[0]), "=r"(r[1]), "=r"(r[2]), "=r"(r[3]) : "r"(a));
}
__device__ __forceinline__ void mma16816(float c[4], const uint32_t a[4],
                                         uint32_t b0, uint32_t b1) {
    asm volatile(
        "mma.sync.aligned.m16n8k16.row.col.f32.f16.f16.f32 "
        "{%0,%1,%2,%3}, {%4,%5,%6,%7}, {%8,%9}, {%0,%1,%2,%3};"
        : "+f"(c[0]), "+f"(c[1]), "+f"(c[2]), "+f"(c[3])
        : "r"(a[0]), "r"(a[1]), "r"(a[2]), "r"(a[3]), "r"(b0), "r"(b1));
}

// ---------------- prep: weights fp32 -> fp16 ----------------
__global__ void convert_weights(const float* __restrict__ W1, const float* __restrict__ W2) {
    int i = blockIdx.x * blockDim.x + threadIdx.x;
    if (i < EMBED * FRONT) g_W1h[i] = __float2half_rn(W1[i]);
    if (i < EMBED * EMBED) g_W2h[i] = __float2half_rn(W2[i]);
}

// ---------------- prep: gather + fp16 convert of embedding rows ----------------
__global__ void __launch_bounds__(256, 4)
gather_fp16(const float* __restrict__ tok, const int* __restrict__ idxs) {
    const int row = blockIdx.x;
    const float4* src = (const float4*)(tok + (size_t)idxs[row] * FRONT);
    uint2* dst = (uint2*)(g_A + (size_t)row * FRONT);
#pragma unroll
    for (int t = 0; t < FRONT / 4 / 256; ++t) {
        int i = t * 256 + threadIdx.x;
        float4 v = src[i];
        __half2 h01 = __floats2half2_rn(v.x, v.y);
        __half2 h23 = __floats2half2_rn(v.z, v.w);
        uint2 o;
        o.x = *(uint32_t*)&h01;
        o.y = *(uint32_t*)&h23;
        dst[i] = o;
    }
}

// ---------------- fragment set for one k16-step (warp tile 64x64) ----------------
struct Frags {
    uint32_t A[4][4], B[4][4];
};

// ---------------- single fp16 mma.sync GEMM, warp 64x64, 2 CTAs/SM ----------------
// acc = sum_k A[m,k] * B[n,k]     (fp16 in, fp32 accum)
// MODE 0: out fp32 = acc + bias
// MODE 1: v = gelu(acc + bias); write fp16 to outH
template <int MODE>
__global__ void __launch_bounds__(THREADS, 2)
gemm_mma(const __half* __restrict__ Ax,
         const __half* __restrict__ Bw,
         const float* __restrict__ bias,
         float* __restrict__ out,
         __half* __restrict__ outH,
         int K) {
    extern __shared__ char sm[];
    const uint32_t sb = smem_u32(sm);

    const int tid = threadIdx.x;
    const int wid = tid >> 5;
    const int l   = tid & 31;
    const int m0  = blockIdx.y * BM;
    const int n0  = blockIdx.x * BN;
    const int wm0 = (wid >> 1) * 64;   // 2 warps over M
    const int wn0 = (wid & 1) * 64;    // 2 warps over N

    // ---- stage loader: 256 rows x 4 chunks = 1024 cp16, 8 per thread ----
    const __half* gptr[8];
    uint32_t      soff[8];
#pragma unroll
    for (int x = 0; x < 8; ++x) {
        int id  = tid + x * THREADS;     // 0..1023
        int row = id >> 2;               // 0..255
        int q   = id & 3;                // 16B chunk in row
        gptr[x] = ((row < BM) ? Ax + (size_t)(m0 + row) * (size_t)K
                              : Bw + (size_t)(n0 + row - BM) * (size_t)K) + q * 8;
        soff[x] = (uint32_t)row * ROWB + (uint32_t)q * 16u;
    }

    auto load_stage = [&](int slot, int c) {
        const uint32_t d = sb + (uint32_t)slot * STAGE;
        const size_t go = (size_t)c * BK;
#pragma unroll
        for (int x = 0; x < 8; ++x)
            cp16(d + soff[x], gptr[x] + go);
    };

    const int r15  = l & 15;
    const int half = l >> 4;

    auto load_frags = [&](Frags& f, uint32_t stageb, int step) {
        const uint32_t koff = (uint32_t)(step * 2 + half) * 16u;
#pragma unroll
        for (int i = 0; i < 4; ++i) {
            uint32_t ad = stageb + OFF_A + (uint32_t)(wm0 + i * 16 + r15) * ROWB + koff;
            ldm4(f.A[i], ad);
        }
#pragma unroll
        for (int p = 0; p < 4; ++p) {
            uint32_t bd = stageb + OFF_B + (uint32_t)(wn0 + p * 16 + r15) * ROWB + koff;
            ldm4(f.B[p], bd);
        }
    };

    float acc[4][8][4];
#pragma unroll
    for (int i = 0; i < 4; ++i)
#pragma unroll
        for (int j = 0; j < 8; ++j)
#pragma unroll
            for (int k = 0; k < 4; ++k) acc[i][j][k] = 0.0f;

    auto mma_frags = [&](const Frags& f) {
        // 32 independent MMAs per step
#pragma unroll
        for (int i = 0; i < 4; ++i)
#pragma unroll
            for (int j = 0; j < 8; ++j) {
                int p = j >> 1, t = j & 1;
                mma16816(acc[i][j], f.A[i], f.B[p][t], f.B[p][t + 2]);
            }
    };

    const int nch = K / BK;

    // ---- prologue: fill stages 0,1; prefetch first fragment set ----
    load_stage(0, 0);
    cp_commit();
    load_stage(1, 1);
    cp_commit();
    asm volatile("cp.async.wait_group 1;");   // chunk 0 resident
    __syncthreads();

    Frags f0, f1;
    load_frags(f0, sb, 0);                     // chunk 0, step 0

    // ---- mainloop (proven R8 depth-2 schedule) ----
    int slot = 0;
#pragma unroll 1
    for (int c = 0; c < nch; ++c) {
        const uint32_t stc = sb + (uint32_t)slot * STAGE;
        const int slot2 = (slot + 2 >= STAGES) ? slot + 2 - STAGES : slot + 2;
        const int slot1 = (slot + 1 >= STAGES) ? slot + 1 - STAGES : slot + 1;

        // prefetch step-1 fragments of this chunk (same stage, already visible)
        load_frags(f1, stc, 1);

        // 32 MMAs on step-0 fragments (loaded last iteration)
        mma_frags(f0);

        // refill ring: chunk c+2 -> slot2
        if (c + 2 < nch) load_stage(slot2, c + 2);
        cp_commit();
        asm volatile("cp.async.wait_group 1;");// all but newest retired -> chunk c+1 done
        __syncthreads();                       // cross-warp visibility of stage c+1

        // prefetch step-0 fragments of chunk c+1
        if (c + 1 < nch) load_frags(f0, sb + (uint32_t)slot1 * STAGE, 0);

        // 32 MMAs on step-1 fragments
        mma_frags(f1);

        slot = slot1;
    }

    // ---- epilogue ----
    const int er = l >> 2;
    const int ec = (l & 3) * 2;
#pragma unroll
    for (int i = 0; i < 4; ++i)
#pragma unroll
        for (int j = 0; j < 8; ++j) {
            int n = n0 + wn0 + j * 8 + ec;
            float bb0 = bias[n], bb1 = bias[n + 1];
#pragma unroll
            for (int h = 0; h < 2; ++h) {
                int m = m0 + wm0 + i * 16 + er + h * 8;
                float v0 = acc[i][j][2 * h]     + bb0;
                float v1 = acc[i][j][2 * h + 1] + bb1;
                if (MODE == 1) {
                    v0 = 0.5f * v0 * (1.0f + erff(v0 * 0.70710678118654752f));
                    v1 = 0.5f * v1 * (1.0f + erff(v1 * 0.70710678118654752f));
                    __half2 hv = __floats2half2_rn(v0, v1);
                    *(uint32_t*)(outH + (size_t)m * EMBED + n) = *(uint32_t*)&hv;
                } else {
                    float2 o; o.x = v0; o.y = v1;
                    *(float2*)(out + (size_t)m * EMBED + n) = o;
                }
            }
        }
}

// ---------------- harness entry ----------------
extern "C" void kernel_launch(void* const* d_in, const int* in_sizes, int n_in,
                              void* d_out, int out_size) {
    const int*   idxs = (const int*)d_in[0];
    const float* tok  = (const float*)d_in[1];
    const float* W1   = (const float*)d_in[2];
    const float* b1   = (const float*)d_in[3];
    const float* W2   = (const float*)d_in[4];
    const float* b2   = (const float*)d_in[5];
    float* out = (float*)d_out;

    void *w1h, *w2h, *a, *y;
    cudaGetSymbolAddress(&w1h, g_W1h);
    cudaGetSymbolAddress(&w2h, g_W2h);
    cudaGetSymbolAddress(&a,   g_A);
    cudaGetSymbolAddress(&y,   g_Y);

    cudaFuncSetAttribute(gemm_mma<1>,
                         cudaFuncAttributeMaxDynamicSharedMemorySize, SMEM_TOTAL);
    cudaFuncSetAttribute(gemm_mma<0>,
                         cudaFuncAttributeMaxDynamicSharedMemorySize, SMEM_TOTAL);

    const int nW = EMBED * FRONT;
    convert_weights<<<(nW + 255) / 256, 256>>>(W1, W2);
    gather_fp16<<<TOKENS, 256>>>(tok, idxs);

    // GEMM1: A @ W1^T + b1, GELU -> Y fp16
    gemm_mma<1><<<dim3(EMBED / BN, TOKENS / BM), THREADS, SMEM_TOTAL>>>(
        (const __half*)a, (const __half*)w1h, b1, nullptr, (__half*)y, FRONT);

    // GEMM2: Y @ W2^T + b2 -> out fp32
    gemm_mma<0><<<dim3(EMBED / BN, TOKENS / BM), THREADS, SMEM_TOTAL>>>(
        (const __half*)y, (const __half*)w2h, b2, out, nullptr, EMBED);
}

// round 15
// speedup vs baseline: 1.0780x; 1.0780x over previous
#include <cuda_runtime.h>
#include <cuda_fp16.h>
#include <cstdint>

#define FRONT 3072
#define EMBED 768
#define TOKENS 16384

// ---------------- device scratch (no dynamic alloc allowed) ----------------
__device__ __half g_W1h[EMBED * FRONT];                 // fp16 weights
__device__ __half g_W2h[EMBED * EMBED];
__device__ __half g_A[(size_t)TOKENS * FRONT];          // gathered embed, fp16
__device__ __half g_Y[(size_t)TOKENS * EMBED];          // GELU(h1), fp16

// ---------------- tiling ----------------
constexpr int BM = 128;
constexpr int BN = 256;
constexpr int BK = 64;              // fp16 K columns per stage (4 k16 steps)
constexpr int THREADS = 256;
constexpr int STAGES = 2;

// 144-byte pitch = 9 x 16B units (odd) -> any 8 consecutive rows at a fixed 16B
// chunk column hit 8 distinct bank groups: ldmatrix conflict-free, NO swizzle.
constexpr int ROWB   = 144;
constexpr int SROWS  = BM + BN;             // 384 rows per stage (A then B)
constexpr int STAGE  = SROWS * ROWB;        // 55296 B
constexpr int SMEM_TOTAL = STAGES * STAGE;  // 110592 B -> 1 CTA/SM
constexpr int OFF_A = 0;
constexpr int OFF_B = BM * ROWB;            // B rows start at row 128

// ---------------- PTX helpers (plain compute_103-legal) ----------------
__device__ __forceinline__ uint32_t smem_u32(const void* p) {
    uint32_t a;
    asm("{ .reg .u64 t; cvta.to.shared.u64 t, %1; cvt.u32.u64 %0, t; }" : "=r"(a) : "l"(p));
    return a;
}
__device__ __forceinline__ void cp16(uint32_t s, const void* g) {
    asm volatile("cp.async.cg.shared.global [%0], [%1], 16;" :: "r"(s), "l"(g));
}
__device__ __forceinline__ void cp_commit() {
    asm volatile("cp.async.commit_group;");
}
__device__ __forceinline__ void ldm4(uint32_t r[4], uint32_t a) {
    asm volatile("ldmatrix.sync.aligned.m8n8.x4.shared.b16 {%0,%1,%2,%3}, [%4];"
                 : "=r"(r[0]), "=r"(r[1]), "=r"(r[2]), "=r"(r[3]) : "r"(a));
}
__device__ __forceinline__ void mma16816(float c[4], const uint32_t a[4],
                                         uint32_t b0, uint32_t b1) {
    asm volatile(
        "mma.sync.aligned.m16n8k16.row.col.f32.f16.f16.f32 "
        "{%0,%1,%2,%3}, {%4,%5,%6,%7}, {%8,%9}, {%0,%1,%2,%3};"
        : "+f"(c[0]), "+f"(c[1]), "+f"(c[2]), "+f"(c[3])
        : "r"(a[0]), "r"(a[1]), "r"(a[2]), "r"(a[3]), "r"(b0), "r"(b1));
}

// ---------------- prep: weights fp32 -> fp16 ----------------
__global__ void convert_weights(const float* __restrict__ W1, const float* __restrict__ W2) {
    int i = blockIdx.x * blockDim.x + threadIdx.x;
    if (i < EMBED * FRONT) g_W1h[i] = __float2half_rn(W1[i]);
    if (i < EMBED * EMBED) g_W2h[i] = __float2half_rn(W2[i]);
}

// ---------------- prep: gather + fp16 convert of embedding rows ----------------
__global__ void __launch_bounds__(256, 4)
gather_fp16(const float* __restrict__ tok, const int* __restrict__ idxs) {
    const int row = blockIdx.x;
    const float4* src = (const float4*)(tok + (size_t)idxs[row] * FRONT);
    uint2* dst = (uint2*)(g_A + (size_t)row * FRONT);
#pragma unroll
    for (int t = 0; t < FRONT / 4 / 256; ++t) {
        int i = t * 256 + threadIdx.x;
        float4 v = src[i];
        __half2 h01 = __floats2half2_rn(v.x, v.y);
        __half2 h23 = __floats2half2_rn(v.z, v.w);
        uint2 o;
        o.x = *(uint32_t*)&h01;
        o.y = *(uint32_t*)&h23;
        dst[i] = o;
    }
}

// ---------------- fragment set for one k16-step (warp tile 64x64) ----------------
struct Frags {
    uint32_t A[4][4], B[4][4];
};

// ---------------- single fp16 mma.sync GEMM, warp 64x64, BK=64 double-buffer ----------------
// acc = sum_k A[m,k] * B[n,k]     (fp16 in, fp32 accum)
// MODE 0: out fp32 = acc + bias
// MODE 1: v = gelu(acc + bias); write fp16 to outH
template <int MODE, int K>
__global__ void __launch_bounds__(THREADS, 1)
gemm_mma(const __half* __restrict__ Ax,
         const __half* __restrict__ Bw,
         const float* __restrict__ bias,
         float* __restrict__ out,
         __half* __restrict__ outH) {
    extern __shared__ char sm[];
    const uint32_t sb = smem_u32(sm);

    const int tid = threadIdx.x;
    const int wid = tid >> 5;
    const int l   = tid & 31;
    const int m0  = blockIdx.y * BM;
    const int n0  = blockIdx.x * BN;
    const int wm0 = (wid >> 2) * 64;   // 2 warps over M
    const int wn0 = (wid & 3) * 64;    // 4 warps over N

    // ---- stage loader: 384 rows x 8 chunks = 3072 cp16, 12 per thread ----
    // x in [0,3]  -> A rows (row = (tid + x*256)>>3 in [x*32, x*32+31] < 128)
    // x in [4,11] -> B rows (row-128)
    // Addresses derived per call (compile-time K) to keep register count low.
    const __half* aBase = Ax + (size_t)m0 * K;
    const __half* bBase = Bw + (size_t)n0 * K;

    auto load_stage = [&](int slot, int c) {
        const uint32_t d = sb + (uint32_t)slot * STAGE;
        const int go = c * BK;
#pragma unroll
        for (int x = 0; x < 12; ++x) {
            int id  = tid + x * THREADS;      // 0..3071
            int row = id >> 3;                // 0..383
            int q   = id & 7;                 // 16B chunk in 128B row
            const __half* g = (x < 4)
                ? aBase + (size_t)row * K + go + q * 8
                : bBase + (size_t)(row - BM) * K + go + q * 8;
            cp16(d + (uint32_t)row * ROWB + (uint32_t)q * 16u, g);
        }
    };

    const int r15  = l & 15;
    const int half = l >> 4;

    auto load_frags = [&](Frags& f, uint32_t stageb, int step) {
        const uint32_t koff = (uint32_t)(step * 2 + half) * 16u;
#pragma unroll
        for (int i = 0; i < 4; ++i) {
            uint32_t ad = stageb + OFF_A + (uint32_t)(wm0 + i * 16 + r15) * ROWB + koff;
            ldm4(f.A[i], ad);
        }
#pragma unroll
        for (int p = 0; p < 4; ++p) {
            uint32_t bd = stageb + OFF_B + (uint32_t)(wn0 + p * 16 + r15) * ROWB + koff;
            ldm4(f.B[p], bd);
        }
    };

    float acc[4][8][4];
#pragma unroll
    for (int i = 0; i < 4; ++i)
#pragma unroll
        for (int j = 0; j < 8; ++j)
#pragma unroll
            for (int k = 0; k < 4; ++k) acc[i][j][k] = 0.0f;

    auto mma_frags = [&](const Frags& f) {
        // 32 independent MMAs per step
#pragma unroll
        for (int i = 0; i < 4; ++i)
#pragma unroll
            for (int j = 0; j < 8; ++j) {
                int p = j >> 1, t = j & 1;
                mma16816(acc[i][j], f.A[i], f.B[p][t], f.B[p][t + 2]);
            }
    };

    constexpr int nch = K / BK;

    // ---- prologue: load chunk 0, prefetch step-0 fragments ----
    load_stage(0, 0);
    cp_commit();
    asm volatile("cp.async.wait_group 0;");
    __syncthreads();

    Frags f0, f1;
    load_frags(f0, sb, 0);

    // ---- mainloop: classic 2-stage double buffer, 4 k16-steps per chunk ----
    int slot = 0;
#pragma unroll 1
    for (int c = 0; c < nch; ++c) {
        const uint32_t stc = sb + (uint32_t)slot * STAGE;

        // issue next chunk's loads into the other slot (it was fully consumed
        // before the barrier at the end of the previous iteration)
        if (c + 1 < nch) load_stage(slot ^ 1, c + 1);
        cp_commit();

        // 4 k16-steps, fragment ping-pong
        load_frags(f1, stc, 1);
        mma_frags(f0);
        load_frags(f0, stc, 2);
        mma_frags(f1);
        load_frags(f1, stc, 3);
        mma_frags(f0);
        mma_frags(f1);

        // chunk c+1 resident; all warps done reading chunk c
        asm volatile("cp.async.wait_group 0;");
        __syncthreads();

        if (c + 1 < nch) load_frags(f0, sb + (uint32_t)(slot ^ 1) * STAGE, 0);
        slot ^= 1;
    }

    // ---- epilogue ----
    const int er = l >> 2;
    const int ec = (l & 3) * 2;
#pragma unroll
    for (int i = 0; i < 4; ++i)
#pragma unroll
        for (int j = 0; j < 8; ++j) {
            int n = n0 + wn0 + j * 8 + ec;
            float bb0 = bias[n], bb1 = bias[n + 1];
#pragma unroll
            for (int h = 0; h < 2; ++h) {
                int m = m0 + wm0 + i * 16 + er + h * 8;
                float v0 = acc[i][j][2 * h]     + bb0;
                float v1 = acc[i][j][2 * h + 1] + bb1;
                if (MODE == 1) {
                    v0 = 0.5f * v0 * (1.0f + erff(v0 * 0.70710678118654752f));
                    v1 = 0.5f * v1 * (1.0f + erff(v1 * 0.70710678118654752f));
                    __half2 hv = __floats2half2_rn(v0, v1);
                    *(uint32_t*)(outH + (size_t)m * EMBED + n) = *(uint32_t*)&hv;
                } else {
                    float2 o; o.x = v0; o.y = v1;
                    *(float2*)(out + (size_t)m * EMBED + n) = o;
                }
            }
        }
}

// ---------------- harness entry ----------------
extern "C" void kernel_launch(void* const* d_in, const int* in_sizes, int n_in,
                              void* d_out, int out_size) {
    const int*   idxs = (const int*)d_in[0];
    const float* tok  = (const float*)d_in[1];
    const float* W1   = (const float*)d_in[2];
    const float* b1   = (const float*)d_in[3];
    const float* W2   = (const float*)d_in[4];
    const float* b2   = (const float*)d_in[5];
    float* out = (float*)d_out;

    void *w1h, *w2h, *a, *y;
    cudaGetSymbolAddress(&w1h, g_W1h);
    cudaGetSymbolAddress(&w2h, g_W2h);
    cudaGetSymbolAddress(&a,   g_A);
    cudaGetSymbolAddress(&y,   g_Y);

    cudaFuncSetAttribute(gemm_mma<1, FRONT>,
                         cudaFuncAttributeMaxDynamicSharedMemorySize, SMEM_TOTAL);
    cudaFuncSetAttribute(gemm_mma<0, EMBED>,
                         cudaFuncAttributeMaxDynamicSharedMemorySize, SMEM_TOTAL);

    const int nW = EMBED * FRONT;
    convert_weights<<<(nW + 255) / 256, 256>>>(W1, W2);
    gather_fp16<<<TOKENS, 256>>>(tok, idxs);

    // GEMM1: A @ W1^T + b1, GELU -> Y fp16
    gemm_mma<1, FRONT><<<dim3(EMBED / BN, TOKENS / BM), THREADS, SMEM_TOTAL>>>(
        (const __half*)a, (const __half*)w1h, b1, nullptr, (__half*)y);

    // GEMM2: Y @ W2^T + b2 -> out fp32
    gemm_mma<0, EMBED><<<dim3(EMBED / BN, TOKENS / BM), THREADS, SMEM_TOTAL>>>(
        (const __half*)y, (const __half*)w2h, b2, out, nullptr);
}

// round 17
// speedup vs baseline: 1.1362x; 1.0541x over previous
#include <cuda_runtime.h>
#include <cuda_fp16.h>
#include <cstdint>

#define FRONT 3072
#define EMBED 768
#define TOKENS 16384

// ---------------- device scratch (no dynamic alloc allowed) ----------------
__device__ __half g_W1h[EMBED * FRONT];                 // fp16 weights
__device__ __half g_W2h[EMBED * EMBED];
__device__ __half g_A[(size_t)TOKENS * FRONT];          // gathered embed, fp16
__device__ __half g_Y[(size_t)TOKENS * EMBED];          // GELU(h1), fp16
__device__ int    g_q;                                  // tile queue counter
__device__ int    g_flag[TOKENS / 128];                 // per m-block G1 completion

// ---------------- tiling (proven R12 config) ----------------
constexpr int BM = 128;
constexpr int BN = 256;
constexpr int BK = 32;              // fp16 K columns per stage (2 k16 steps)
constexpr int THREADS = 256;
constexpr int STAGES = 3;

constexpr int ROWB   = 80;          // 5x16B (odd) -> ldmatrix conflict-free, no swizzle
constexpr int SROWS  = BM + BN;             // 384 rows per stage (A then B)
constexpr int STAGE  = SROWS * ROWB;        // 30720 B
constexpr int SMEM_TOTAL = STAGES * STAGE;  // 92160 B -> 1 CTA/SM
constexpr int OFF_A = 0;
constexpr int OFF_B = BM * ROWB;

// tiles: G1 = 384 (grid 3 x 128), then G2 = 384
constexpr int NT1 = (EMBED / BN) * (TOKENS / BM);   // 384
constexpr int NT  = 2 * NT1;                        // 768

// ---------------- PTX helpers (plain compute_103-legal) ----------------
__device__ __forceinline__ uint32_t smem_u32(const void* p) {
    uint32_t a;
    asm("{ .reg .u64 t; cvta.to.shared.u64 t, %1; cvt.u32.u64 %0, t; }" : "=r"(a) : "l"(p));
    return a;
}
__device__ __forceinline__ void cp16(uint32_t s, const void* g) {
    asm volatile("cp.async.cg.shared.global [%0], [%1], 16;" :: "r"(s), "l"(g));
}
__device__ __forceinline__ void cp_commit() {
    asm volatile("cp.async.commit_group;");
}
__device__ __forceinline__ void ldm4(uint32_t r[4], uint32_t a) {
    asm volatile("ldmatrix.sync.aligned.m8n8.x4.shared.b16 {%0,%1,%2,%3}, [%4];"
                 : "=r"(r[0]), "=r"(r[1]), "=r"(r[2]), "=r"(r[3]) : "r"(a));
}
__device__ __forceinline__ void mma16816(float c[4], const uint32_t a[4],
                                         uint32_t b0, uint32_t b1) {
    asm volatile(
        "mma.sync.aligned.m16n8k16.row.col.f32.f16.f16.f32 "
        "{%0,%1,%2,%3}, {%4,%5,%6,%7}, {%8,%9}, {%0,%1,%2,%3};"
        : "+f"(c[0]), "+f"(c[1]), "+f"(c[2]), "+f"(c[3])
        : "r"(a[0]), "r"(a[1]), "r"(a[2]), "r"(a[3]), "r"(b0), "r"(b1));
}

// ---------------- fused prep: gather+convert A, convert W, reset queue ----------------
constexpr int GATHER_BLKS = TOKENS;                       // 16384
constexpr int CONV_BLKS   = (EMBED * FRONT + 255) / 256;  // 9216
__global__ void __launch_bounds__(256, 4)
prep(const float* __restrict__ tok, const int* __restrict__ idxs,
     const float* __restrict__ W1, const float* __restrict__ W2) {
    const int b = blockIdx.x;
    if (b < GATHER_BLKS) {
        const float4* src = (const float4*)(tok + (size_t)idxs[b] * FRONT);
        uint2* dst = (uint2*)(g_A + (size_t)b * FRONT);
#pragma unroll
        for (int t = 0; t < FRONT / 4 / 256; ++t) {
            int i = t * 256 + threadIdx.x;
            float4 v = src[i];
            __half2 h01 = __floats2half2_rn(v.x, v.y);
            __half2 h23 = __floats2half2_rn(v.z, v.w);
            uint2 o;
            o.x = *(uint32_t*)&h01;
            o.y = *(uint32_t*)&h23;
            dst[i] = o;
        }
    } else if (b < GATHER_BLKS + CONV_BLKS) {
        int i = (b - GATHER_BLKS) * 256 + threadIdx.x;
        if (i < EMBED * FRONT) g_W1h[i] = __float2half_rn(W1[i]);
        if (i < EMBED * EMBED) g_W2h[i] = __float2half_rn(W2[i]);
    } else {
        if (threadIdx.x < TOKENS / 128) g_flag[threadIdx.x] = 0;
        if (threadIdx.x == 128) g_q = 0;
    }
}

// ---------------- fragment set for one k16-step (warp tile 64x64) ----------------
struct Frags {
    uint32_t A[4][4], B[4][4];
};

// ---------------- persistent mega-kernel: G1 tiles then G2 tiles ----------------
__global__ void __launch_bounds__(THREADS, 1)
mega(const float* __restrict__ b1, const float* __restrict__ b2,
     float* __restrict__ out) {
    extern __shared__ char sm[];
    __shared__ int s_tile;
    const uint32_t sb = smem_u32(sm);

    const int tid = threadIdx.x;
    const int wid = tid >> 5;
    const int l   = tid & 31;
    const int wm0 = (wid >> 2) * 64;   // 2 warps over M
    const int wn0 = (wid & 3) * 64;    // 4 warps over N
    const int r15  = l & 15;
    const int half = l >> 4;

    for (;;) {
        if (tid == 0) s_tile = atomicAdd(&g_q, 1);
        __syncthreads();
        const int t = s_tile;
        __syncthreads();
        if (t >= NT) break;

        const bool g1 = (t < NT1);
        const int  tt = g1 ? t : t - NT1;
        const int  nb = tt % (EMBED / BN);
        const int  mb = tt / (EMBED / BN);
        const int  m0 = mb * BM;
        const int  n0 = nb * BN;
        const int  K  = g1 ? FRONT : EMBED;
        const __half* Ax = g1 ? g_A + (size_t)m0 * FRONT
                              : g_Y + (size_t)m0 * EMBED;
        const __half* Bw = g1 ? g_W1h + (size_t)n0 * FRONT
                              : g_W2h + (size_t)n0 * EMBED;

        // ---- G2 dependency: all 3 G1 tiles of this m-block done ----
        if (!g1) {
            if (tid == 0) {
                while (atomicAdd(&g_flag[mb], 0) < (EMBED / BN)) __nanosleep(64);
                __threadfence();
            }
            __syncthreads();
        }

        // ---- per-tile loader setup: 384 rows x 4 chunks = 1536 cp16, 6/thread ----
        const __half* gptr[6];
        uint32_t      soff[6];
#pragma unroll
        for (int x = 0; x < 6; ++x) {
            int id  = tid + x * THREADS;     // 0..1535
            int row = id >> 2;               // 0..383
            int q   = id & 3;
            gptr[x] = ((row < BM) ? Ax + (size_t)row * K
                                  : Bw + (size_t)(row - BM) * K) + q * 8;
            soff[x] = (uint32_t)row * ROWB + (uint32_t)q * 16u;
        }

        auto load_stage = [&](int slot, int c) {
            const uint32_t d = sb + (uint32_t)slot * STAGE;
            const int go = c * BK;
#pragma unroll
            for (int x = 0; x < 6; ++x)
                cp16(d + soff[x], gptr[x] + go);
        };

        auto load_frags = [&](Frags& f, uint32_t stageb, int step) {
            const uint32_t koff = (uint32_t)(step * 2 + half) * 16u;
#pragma unroll
            for (int i = 0; i < 4; ++i) {
                uint32_t ad = stageb + OFF_A + (uint32_t)(wm0 + i * 16 + r15) * ROWB + koff;
                ldm4(f.A[i], ad);
            }
#pragma unroll
            for (int p = 0; p < 4; ++p) {
                uint32_t bd = stageb + OFF_B + (uint32_t)(wn0 + p * 16 + r15) * ROWB + koff;
                ldm4(f.B[p], bd);
            }
        };

        float acc[4][8][4];
#pragma unroll
        for (int i = 0; i < 4; ++i)
#pragma unroll
            for (int j = 0; j < 8; ++j)
#pragma unroll
                for (int k = 0; k < 4; ++k) acc[i][j][k] = 0.0f;

        auto mma_frags = [&](const Frags& f) {
#pragma unroll
            for (int i = 0; i < 4; ++i)
#pragma unroll
                for (int j = 0; j < 8; ++j) {
                    int p = j >> 1, tq = j & 1;
                    mma16816(acc[i][j], f.A[i], f.B[p][tq], f.B[p][tq + 2]);
                }
        };

        const int nch = K / BK;

        // ---- prologue (R12): fill stages 0,1; prefetch first fragments ----
        load_stage(0, 0);
        cp_commit();
        load_stage(1, 1);
        cp_commit();
        asm volatile("cp.async.wait_group 1;");
        __syncthreads();

        Frags f0, f1;
        load_frags(f0, sb, 0);

        // ---- mainloop (proven R12 depth-2 schedule) ----
        int slot = 0;
#pragma unroll 1
        for (int c = 0; c < nch; ++c) {
            const uint32_t stc = sb + (uint32_t)slot * STAGE;
            const int slot2 = (slot + 2 >= STAGES) ? slot + 2 - STAGES : slot + 2;
            const int slot1 = (slot + 1 >= STAGES) ? slot + 1 - STAGES : slot + 1;

            load_frags(f1, stc, 1);
            mma_frags(f0);

            if (c + 2 < nch) load_stage(slot2, c + 2);
            cp_commit();
            asm volatile("cp.async.wait_group 1;");
            __syncthreads();

            if (c + 1 < nch) load_frags(f0, sb + (uint32_t)slot1 * STAGE, 0);
            mma_frags(f1);

            slot = slot1;
        }

        // ---- epilogue ----
        const float* bias = g1 ? b1 : b2;
        const int er = l >> 2;
        const int ec = (l & 3) * 2;
#pragma unroll
        for (int i = 0; i < 4; ++i)
#pragma unroll
            for (int j = 0; j < 8; ++j) {
                int n = n0 + wn0 + j * 8 + ec;
                float bb0 = bias[n], bb1 = bias[n + 1];
#pragma unroll
                for (int h = 0; h < 2; ++h) {
                    int m = m0 + wm0 + i * 16 + er + h * 8;
                    float v0 = acc[i][j][2 * h]     + bb0;
                    float v1 = acc[i][j][2 * h + 1] + bb1;
                    if (g1) {
                        v0 = 0.5f * v0 * (1.0f + erff(v0 * 0.70710678118654752f));
                        v1 = 0.5f * v1 * (1.0f + erff(v1 * 0.70710678118654752f));
                        __half2 hv = __floats2half2_rn(v0, v1);
                        *(uint32_t*)(g_Y + (size_t)m * EMBED + n) = *(uint32_t*)&hv;
                    } else {
                        float2 o; o.x = v0; o.y = v1;
                        *(float2*)(out + (size_t)m * EMBED + n) = o;
                    }
                }
            }

        // ---- drain + publish (release) ----
        asm volatile("cp.async.wait_group 0;");
        __threadfence();
        __syncthreads();
        if (g1 && tid == 0) atomicAdd(&g_flag[mb], 1);
    }
}

// ---------------- harness entry ----------------
extern "C" void kernel_launch(void* const* d_in, const int* in_sizes, int n_in,
                              void* d_out, int out_size) {
    const int*   idxs = (const int*)d_in[0];
    const float* tok  = (const float*)d_in[1];
    const float* W1   = (const float*)d_in[2];
    const float* b1   = (const float*)d_in[3];
    const float* W2   = (const float*)d_in[4];
    const float* b2   = (const float*)d_in[5];
    float* out = (float*)d_out;

    cudaFuncSetAttribute(mega, cudaFuncAttributeMaxDynamicSharedMemorySize, SMEM_TOTAL);

    int nsm = 148;
    cudaDeviceGetAttribute(&nsm, cudaDevAttrMultiProcessorCount, 0);

    prep<<<GATHER_BLKS + CONV_BLKS + 1, 256>>>(tok, idxs, W1, W2);
    mega<<<nsm, THREADS, SMEM_TOTAL>>>(b1, b2, out);
}